// round 6
// baseline (speedup 1.0000x reference)
#include <cuda_runtime.h>
#include <cuda_bf16.h>
#include <cstdint>
#include <math.h>

typedef uint32_t u32;

#define BB 8
#define NN 4096
#define CC 128
#define QT 256              // query rows per CTA (16 warps x 16 rows)
#define KTT 64
#define NTILE (NN / KTT)
#define EOFF 10.0f

__device__ __nv_bfloat16 g_q[BB * NN * CC];
__device__ __nv_bfloat16 g_k[BB * NN * CC];
__device__ __nv_bfloat16 g_v[BB * NN * CC];

// ---- attn smem ----
#define QS_OFF  0u          // 256 rows x 256B = 64KB
#define KS_OFF  65536u      // 2 x 16KB
#define VS_OFF  98304u      // 2 x 16KB
#define BN_OFF  131072u     // 512B inv + 512B add
#define SMEM_ATTN 132096
// ---- qkv smem ----
#define XS_OFF  0u          // 128 rows x 256B bf16
#define WS_OFF  32768u      // 3 x 32KB bf16
#define SMEM_QKV 131072

// ---------------- helpers ----------------
__device__ __forceinline__ u32 s2u(const void* p) {
    u32 a; asm("{ .reg .u64 t; cvta.to.shared.u64 t, %1; cvt.u32.u64 %0, t; }" : "=r"(a) : "l"(p));
    return a;
}
__device__ __forceinline__ u32 so(u32 row, u32 c8) {      // 256B rows, XOR swizzle
    return row * 256u + ((c8 ^ (row & 7u)) * 16u);
}
__device__ __forceinline__ void cpa16(u32 dst, const void* src) {
    asm volatile("cp.async.cg.shared.global [%0], [%1], 16;" :: "r"(dst), "l"(src));
}
__device__ __forceinline__ void cp_commit() { asm volatile("cp.async.commit_group;" ::: "memory"); }
template <int N> __device__ __forceinline__ void cp_wait() {
    asm volatile("cp.async.wait_group %0;" :: "n"(N) : "memory");
}
__device__ __forceinline__ void ldsm4(u32 addr, u32* r) {
    asm volatile("ldmatrix.sync.aligned.m8n8.x4.shared.b16 {%0,%1,%2,%3}, [%4];"
                 : "=r"(r[0]), "=r"(r[1]), "=r"(r[2]), "=r"(r[3]) : "r"(addr));
}
__device__ __forceinline__ void ldsm4t(u32 addr, u32* r) {
    asm volatile("ldmatrix.sync.aligned.m8n8.x4.trans.shared.b16 {%0,%1,%2,%3}, [%4];"
                 : "=r"(r[0]), "=r"(r[1]), "=r"(r[2]), "=r"(r[3]) : "r"(addr));
}
__device__ __forceinline__ void mmabf(float* c, const u32* a, u32 b0, u32 b1) {
    asm volatile("mma.sync.aligned.m16n8k16.row.col.f32.bf16.bf16.f32 "
                 "{%0,%1,%2,%3}, {%4,%5,%6,%7}, {%8,%9}, {%0,%1,%2,%3};"
                 : "+f"(c[0]), "+f"(c[1]), "+f"(c[2]), "+f"(c[3])
                 : "r"(a[0]), "r"(a[1]), "r"(a[2]), "r"(a[3]), "r"(b0), "r"(b1));
}
__device__ __forceinline__ u32 cvtbf(float hi, float lo) {
    u32 d; asm("cvt.rn.bf16x2.f32 %0, %1, %2;" : "=r"(d) : "f"(hi), "f"(lo)); return d;
}

// =====================================================================
// Kernel 1: QKV projection via bf16 mma.sync.
// grid = 256 (128 rows each), block = 256 (8 warps x 16 rows).
// x, w converted to bf16 in smem; B = w[c][d] loaded with ldmatrix.trans.
// =====================================================================
__global__ void __launch_bounds__(256, 1) qkv_mma(
    const float* __restrict__ x,
    const float* __restrict__ wq, const float* __restrict__ bq,
    const float* __restrict__ wk, const float* __restrict__ bk,
    const float* __restrict__ wv, const float* __restrict__ bv)
{
    extern __shared__ char smc[];
    const u32 sb = s2u(smc);
    const int tid = threadIdx.x, w = tid >> 5, lane = tid & 31;
    const int r8 = lane & 7, sel = lane >> 3;
    const int row0 = blockIdx.x * 128;

    // ---- load & convert x tile [128 x 128] ----
    #pragma unroll
    for (int i = 0; i < 8; i++) {
        int idx = tid + 256 * i; u32 r = (u32)(idx >> 4), c8 = (u32)(idx & 15);
        const float* p = x + (size_t)(row0 + r) * CC + 8 * c8;
        float4 a = *(const float4*)p;
        float4 bqv = *(const float4*)(p + 4);
        uint4 o;
        o.x = cvtbf(a.y, a.x);   o.y = cvtbf(a.w, a.z);
        o.z = cvtbf(bqv.y, bqv.x); o.w = cvtbf(bqv.w, bqv.z);
        *(uint4*)(smc + XS_OFF + so(r, c8)) = o;
    }
    // ---- load & convert 3 weight matrices [128 x 128] each ----
    const float* ws[3] = { wq, wk, wv };
    #pragma unroll
    for (int m = 0; m < 3; m++) {
        const float* wp = ws[m];
        #pragma unroll
        for (int i = 0; i < 8; i++) {
            int idx = tid + 256 * i; u32 r = (u32)(idx >> 4), c8 = (u32)(idx & 15);
            const float* p = wp + (size_t)r * CC + 8 * c8;
            float4 a = *(const float4*)p;
            float4 bqv = *(const float4*)(p + 4);
            uint4 o;
            o.x = cvtbf(a.y, a.x);   o.y = cvtbf(a.w, a.z);
            o.z = cvtbf(bqv.y, bqv.x); o.w = cvtbf(bqv.w, bqv.z);
            *(uint4*)(smc + WS_OFF + (u32)m * 32768u + so(r, c8)) = o;
        }
    }
    __syncthreads();

    // A fragments for this warp's 16 rows
    u32 qa[8][4];
    #pragma unroll
    for (int s = 0; s < 8; s++) {
        u32 r = (u32)(w * 16 + r8 + (sel & 1) * 8);
        u32 ch = (u32)(2 * s + (sel >> 1));
        ldsm4(sb + XS_OFF + so(r, ch), qa[s]);
    }

    __nv_bfloat16* outs[3] = { g_q, g_k, g_v };
    const float* biases[3] = { bq, bk, bv };
    const int rr = lane >> 2, cq = (lane & 3) * 2;
    const int ra = blockIdx.x * 128 + w * 16 + rr;

    #pragma unroll
    for (int m = 0; m < 3; m++) {
        const u32 wb = sb + WS_OFF + (u32)m * 32768u;
        const float qs = (m == 0) ? 0.088388347648318447f : 1.0f;
        float acc[16][4];
        #pragma unroll
        for (int g = 0; g < 16; g++)
            { acc[g][0] = 0.f; acc[g][1] = 0.f; acc[g][2] = 0.f; acc[g][3] = 0.f; }

        #pragma unroll
        for (int gp = 0; gp < 8; gp++) {
            #pragma unroll
            for (int s = 0; s < 8; s++) {
                u32 kr = (u32)(s * 16 + r8 + (sel & 1) * 8);
                u32 ch = (u32)(2 * gp + (sel >> 1));
                u32 bf[4];
                ldsm4t(wb + so(kr, ch), bf);
                mmabf(acc[2 * gp],     qa[s], bf[0], bf[1]);
                mmabf(acc[2 * gp + 1], qa[s], bf[2], bf[3]);
            }
        }

        const float* bias = biases[m];
        __nv_bfloat16* og = outs[m];
        #pragma unroll
        for (int g = 0; g < 16; g++) {
            int c = g * 8 + cq;
            float b0 = __ldg(bias + c), b1 = __ldg(bias + c + 1);
            u32 v0 = cvtbf((acc[g][1] + b1) * qs, (acc[g][0] + b0) * qs);
            u32 v1 = cvtbf((acc[g][3] + b1) * qs, (acc[g][2] + b0) * qs);
            *(u32*)&og[(size_t)ra * CC + c] = v0;
            *(u32*)&og[(size_t)(ra + 8) * CC + c] = v1;
        }
    }
}

// =====================================================================
// K+V tile loader (one cp.async group), 512 threads
// =====================================================================
__device__ __forceinline__ void ldKV(u32 sb, const __nv_bfloat16* kg,
                                     const __nv_bfloat16* vg, int tid, int buf)
{
    u32 kb = sb + KS_OFF + (u32)buf * 16384u;
    u32 vb = sb + VS_OFF + (u32)buf * 16384u;
    #pragma unroll
    for (int i = 0; i < 2; i++) {
        int idx = tid + 512 * i; u32 row = (u32)(idx >> 4), c8 = (u32)(idx & 15);
        cpa16(kb + so(row, c8), kg + (size_t)row * CC + 8 * c8);
    }
    #pragma unroll
    for (int i = 0; i < 2; i++) {
        int idx = tid + 512 * i; u32 row = (u32)(idx >> 4), c8 = (u32)(idx & 15);
        cpa16(vb + so(row, c8), vg + (size_t)row * CC + 8 * c8);
    }
    cp_commit();
}

// =====================================================================
// Kernel 2: bf16 mma.sync flash attention + residual + BN
// grid (16, 8) = 128 CTAs, 512 threads (16 warps x 16 query rows)
// =====================================================================
__global__ void __launch_bounds__(512, 1) attn_mma(
    const float* __restrict__ x,
    const float* __restrict__ gamma, const float* __restrict__ beta,
    const float* __restrict__ mmean, const float* __restrict__ mvar,
    float* __restrict__ out)
{
    extern __shared__ char smc[];
    const u32 sb = s2u(smc);
    const int tid = threadIdx.x, w = tid >> 5, lane = tid & 31;
    const int r8 = lane & 7, sel = lane >> 3;
    const int b = blockIdx.y, q0 = blockIdx.x * QT;
    const size_t base = (size_t)b * NN * CC;

    if (tid < 128) {
        float iv = gamma[tid] * rsqrtf(mvar[tid] + 1e-3f);
        ((float*)(smc + BN_OFF))[tid] = iv;
        ((float*)(smc + BN_OFF + 512))[tid] = beta[tid] - mmean[tid] * iv;
    }

    // prologue: Q (group 0), KV0 (group 1), KV1 (group 2)
    {
        const __nv_bfloat16* qg = g_q + base + (size_t)q0 * CC;
        #pragma unroll
        for (int i = 0; i < 8; i++) {
            int idx = tid + 512 * i; u32 row = (u32)(idx >> 4), c8 = (u32)(idx & 15);
            cpa16(sb + QS_OFF + so(row, c8), qg + (size_t)row * CC + 8 * c8);
        }
        cp_commit();
    }
    ldKV(sb, g_k + base, g_v + base, tid, 0);
    ldKV(sb, g_k + base + (size_t)KTT * CC, g_v + base + (size_t)KTT * CC, tid, 1);

    cp_wait<2>();
    __syncthreads();

    u32 qa[8][4];
    #pragma unroll
    for (int s = 0; s < 8; s++) {
        u32 row = (u32)(w * 16 + r8 + (sel & 1) * 8);
        u32 ch  = (u32)(2 * s + (sel >> 1));
        ldsm4(sb + QS_OFF + so(row, ch), qa[s]);
    }

    float o[16][4];
    #pragma unroll
    for (int g = 0; g < 16; g++)
        { o[g][0] = 0.f; o[g][1] = 0.f; o[g][2] = 0.f; o[g][3] = 0.f; }
    float lr0 = 0.f, lr1 = 0.f;

    for (int j = 0; j < NTILE; j++) {
        cp_wait<1>();
        __syncthreads();
        const u32 kb = sb + KS_OFF + (u32)(j & 1) * 16384u;
        const u32 vb = sb + VS_OFF + (u32)(j & 1) * 16384u;

        // ---- S = Q K^T ----
        float sc[8][4];
        #pragma unroll
        for (int g = 0; g < 8; g++)
            { sc[g][0] = 0.f; sc[g][1] = 0.f; sc[g][2] = 0.f; sc[g][3] = 0.f; }

        #pragma unroll
        for (int gp = 0; gp < 4; gp++) {
            #pragma unroll
            for (int s = 0; s < 8; s++) {
                u32 key = (u32)(gp * 16 + r8 + (sel >> 1) * 8);
                u32 ch  = (u32)(2 * s + (sel & 1));
                u32 kf[4];
                ldsm4(kb + so(key, ch), kf);
                mmabf(sc[2 * gp],     qa[s], kf[0], kf[1]);
                mmabf(sc[2 * gp + 1], qa[s], kf[2], kf[3]);
            }
        }

        // ---- softmax (fixed offset), pack P as A-fragments ----
        u32 p[4][4];
        #pragma unroll
        for (int g = 0; g < 8; g++) {
            float e0 = __expf(sc[g][0] - EOFF);
            float e1 = __expf(sc[g][1] - EOFF);
            float e2 = __expf(sc[g][2] - EOFF);
            float e3 = __expf(sc[g][3] - EOFF);
            lr0 += e0 + e1;
            lr1 += e2 + e3;
            p[g >> 1][(g & 1) ? 2 : 0] = cvtbf(e1, e0);
            p[g >> 1][(g & 1) ? 3 : 1] = cvtbf(e3, e2);
        }

        // ---- O += P V ----
        #pragma unroll
        for (int s = 0; s < 4; s++) {
            #pragma unroll
            for (int gp = 0; gp < 8; gp++) {
                u32 key = (u32)(s * 16 + r8 + (sel & 1) * 8);
                u32 ch  = (u32)(2 * gp + (sel >> 1));
                u32 vf[4];
                ldsm4t(vb + so(key, ch), vf);
                mmabf(o[2 * gp],     p[s], vf[0], vf[1]);
                mmabf(o[2 * gp + 1], p[s], vf[2], vf[3]);
            }
        }

        __syncthreads();
        if (j + 2 < NTILE)
            ldKV(sb, g_k + base + (size_t)(j + 2) * KTT * CC,
                     g_v + base + (size_t)(j + 2) * KTT * CC, tid, j & 1);
    }

    // ---- epilogue ----
    lr0 += __shfl_xor_sync(0xffffffffu, lr0, 1);
    lr0 += __shfl_xor_sync(0xffffffffu, lr0, 2);
    lr1 += __shfl_xor_sync(0xffffffffu, lr1, 1);
    lr1 += __shfl_xor_sync(0xffffffffu, lr1, 2);
    const float il0 = 1.0f / lr0, il1 = 1.0f / lr1;

    const float* invc = (const float*)(smc + BN_OFF);
    const float* addc = (const float*)(smc + BN_OFF + 512);
    const int rr = lane >> 2, cq = (lane & 3) * 2;
    const int row0g = q0 + w * 16 + rr, row1g = row0g + 8;

    #pragma unroll
    for (int g = 0; g < 16; g++) {
        int c = g * 8 + cq;
        float2 x0 = *(const float2*)&x[base + (size_t)row0g * CC + c];
        float2 x1 = *(const float2*)&x[base + (size_t)row1g * CC + c];
        float2 v0, v1;
        v0.x = (o[g][0] * il0 + x0.x) * invc[c]     + addc[c];
        v0.y = (o[g][1] * il0 + x0.y) * invc[c + 1] + addc[c + 1];
        v1.x = (o[g][2] * il1 + x1.x) * invc[c]     + addc[c];
        v1.y = (o[g][3] * il1 + x1.y) * invc[c + 1] + addc[c + 1];
        *(float2*)&out[base + (size_t)row0g * CC + c] = v0;
        *(float2*)&out[base + (size_t)row1g * CC + c] = v1;
    }
}

// =====================================================================
extern "C" void kernel_launch(void* const* d_in, const int* in_sizes, int n_in,
                              void* d_out, int out_size)
{
    const float* x     = (const float*)d_in[0];
    const float* wq    = (const float*)d_in[1];
    const float* bq    = (const float*)d_in[2];
    const float* wk    = (const float*)d_in[3];
    const float* bk    = (const float*)d_in[4];
    const float* wv    = (const float*)d_in[5];
    const float* bv    = (const float*)d_in[6];
    const float* gamma = (const float*)d_in[7];
    const float* beta  = (const float*)d_in[8];
    const float* mmean = (const float*)d_in[9];
    const float* mvar  = (const float*)d_in[10];
    float* out = (float*)d_out;

    cudaFuncSetAttribute(qkv_mma, cudaFuncAttributeMaxDynamicSharedMemorySize, SMEM_QKV);
    cudaFuncSetAttribute(attn_mma, cudaFuncAttributeMaxDynamicSharedMemorySize, SMEM_ATTN);

    qkv_mma<<<(BB * NN) / 128, 256, SMEM_QKV>>>(x, wq, bq, wk, bk, wv, bv);
    attn_mma<<<dim3(NN / QT, BB), 512, SMEM_ATTN>>>(x, gamma, beta, mmean, mvar, out);
}

// round 7
// speedup vs baseline: 1.2630x; 1.2630x over previous
#include <cuda_runtime.h>
#include <cuda_bf16.h>
#include <cstdint>
#include <math.h>

typedef uint32_t u32;

#define BB 8
#define NN 4096
#define CC 128
#define QT 128              // query rows per CTA (8 warps x 16 rows)
#define KTT 64
#define NTILE (NN / KTT)
#define EOFF 10.0f
#define LOG2E 1.4426950408889634f

__device__ __nv_bfloat16 g_q[BB * NN * CC];
__device__ __nv_bfloat16 g_k[BB * NN * CC];
__device__ __nv_bfloat16 g_v[BB * NN * CC];

// ---- attn smem: Q 32KB | K 3x16KB | V 3x16KB | BN 1KB ----
#define QS_OFF  0u
#define KS_OFF  32768u
#define VS_OFF  81920u
#define BN_OFF  131072u
#define SMEM_ATTN 132096
// ---- qkv smem ----
#define XS_OFF  0u
#define WS_OFF  32768u
#define SMEM_QKV 131072

// ---------------- helpers ----------------
__device__ __forceinline__ u32 s2u(const void* p) {
    u32 a; asm("{ .reg .u64 t; cvta.to.shared.u64 t, %1; cvt.u32.u64 %0, t; }" : "=r"(a) : "l"(p));
    return a;
}
__device__ __forceinline__ u32 so(u32 row, u32 c8) {      // 256B rows, XOR swizzle
    return row * 256u + ((c8 ^ (row & 7u)) * 16u);
}
__device__ __forceinline__ void cpa16(u32 dst, const void* src) {
    asm volatile("cp.async.cg.shared.global [%0], [%1], 16;" :: "r"(dst), "l"(src));
}
__device__ __forceinline__ void cp_commit() { asm volatile("cp.async.commit_group;" ::: "memory"); }
template <int N> __device__ __forceinline__ void cp_wait() {
    asm volatile("cp.async.wait_group %0;" :: "n"(N) : "memory");
}
__device__ __forceinline__ void ldsm4(u32 addr, u32* r) {
    asm volatile("ldmatrix.sync.aligned.m8n8.x4.shared.b16 {%0,%1,%2,%3}, [%4];"
                 : "=r"(r[0]), "=r"(r[1]), "=r"(r[2]), "=r"(r[3]) : "r"(addr));
}
__device__ __forceinline__ void ldsm4t(u32 addr, u32* r) {
    asm volatile("ldmatrix.sync.aligned.m8n8.x4.trans.shared.b16 {%0,%1,%2,%3}, [%4];"
                 : "=r"(r[0]), "=r"(r[1]), "=r"(r[2]), "=r"(r[3]) : "r"(addr));
}
__device__ __forceinline__ void mmabf(float* c, const u32* a, u32 b0, u32 b1) {
    asm volatile("mma.sync.aligned.m16n8k16.row.col.f32.bf16.bf16.f32 "
                 "{%0,%1,%2,%3}, {%4,%5,%6,%7}, {%8,%9}, {%0,%1,%2,%3};"
                 : "+f"(c[0]), "+f"(c[1]), "+f"(c[2]), "+f"(c[3])
                 : "r"(a[0]), "r"(a[1]), "r"(a[2]), "r"(a[3]), "r"(b0), "r"(b1));
}
__device__ __forceinline__ u32 cvtbf(float hi, float lo) {
    u32 d; asm("cvt.rn.bf16x2.f32 %0, %1, %2;" : "=r"(d) : "f"(hi), "f"(lo)); return d;
}
__device__ __forceinline__ float ex2(float x) {
    float r; asm("ex2.approx.f32 %0, %1;" : "=f"(r) : "f"(x)); return r;
}

// =====================================================================
// Kernel 1: QKV projection via bf16 mma.sync (proven ~24us).
// grid = 256, block = 256 (8 warps x 16 rows of a 128-row tile).
// =====================================================================
__global__ void __launch_bounds__(256, 1) qkv_mma(
    const float* __restrict__ x,
    const float* __restrict__ wq, const float* __restrict__ bq,
    const float* __restrict__ wk, const float* __restrict__ bk,
    const float* __restrict__ wv, const float* __restrict__ bv)
{
    extern __shared__ char smc[];
    const u32 sb = s2u(smc);
    const int tid = threadIdx.x, w = tid >> 5, lane = tid & 31;
    const int r8 = lane & 7, sel = lane >> 3;
    const int row0 = blockIdx.x * 128;

    #pragma unroll
    for (int i = 0; i < 8; i++) {
        int idx = tid + 256 * i; u32 r = (u32)(idx >> 4), c8 = (u32)(idx & 15);
        const float* p = x + (size_t)(row0 + r) * CC + 8 * c8;
        float4 a = *(const float4*)p;
        float4 bv4 = *(const float4*)(p + 4);
        uint4 o;
        o.x = cvtbf(a.y, a.x);     o.y = cvtbf(a.w, a.z);
        o.z = cvtbf(bv4.y, bv4.x); o.w = cvtbf(bv4.w, bv4.z);
        *(uint4*)(smc + XS_OFF + so(r, c8)) = o;
    }
    const float* ws[3] = { wq, wk, wv };
    #pragma unroll
    for (int m = 0; m < 3; m++) {
        const float* wp = ws[m];
        #pragma unroll
        for (int i = 0; i < 8; i++) {
            int idx = tid + 256 * i; u32 r = (u32)(idx >> 4), c8 = (u32)(idx & 15);
            const float* p = wp + (size_t)r * CC + 8 * c8;
            float4 a = *(const float4*)p;
            float4 bv4 = *(const float4*)(p + 4);
            uint4 o;
            o.x = cvtbf(a.y, a.x);     o.y = cvtbf(a.w, a.z);
            o.z = cvtbf(bv4.y, bv4.x); o.w = cvtbf(bv4.w, bv4.z);
            *(uint4*)(smc + WS_OFF + (u32)m * 32768u + so(r, c8)) = o;
        }
    }
    __syncthreads();

    u32 qa[8][4];
    #pragma unroll
    for (int s = 0; s < 8; s++) {
        u32 r = (u32)(w * 16 + r8 + (sel & 1) * 8);
        u32 ch = (u32)(2 * s + (sel >> 1));
        ldsm4(sb + XS_OFF + so(r, ch), qa[s]);
    }

    __nv_bfloat16* outs[3] = { g_q, g_k, g_v };
    const float* biases[3] = { bq, bk, bv };
    const int rr = lane >> 2, cq = (lane & 3) * 2;
    const int ra = row0 + w * 16 + rr;

    #pragma unroll
    for (int m = 0; m < 3; m++) {
        const u32 wb = sb + WS_OFF + (u32)m * 32768u;
        const float qs = (m == 0) ? 0.088388347648318447f : 1.0f;
        float acc[16][4];
        #pragma unroll
        for (int g = 0; g < 16; g++)
            { acc[g][0] = 0.f; acc[g][1] = 0.f; acc[g][2] = 0.f; acc[g][3] = 0.f; }

        #pragma unroll
        for (int gp = 0; gp < 8; gp++) {
            #pragma unroll
            for (int s = 0; s < 8; s++) {
                u32 kr = (u32)(s * 16 + r8 + (sel & 1) * 8);
                u32 ch = (u32)(2 * gp + (sel >> 1));
                u32 bf[4];
                ldsm4t(wb + so(kr, ch), bf);
                mmabf(acc[2 * gp],     qa[s], bf[0], bf[1]);
                mmabf(acc[2 * gp + 1], qa[s], bf[2], bf[3]);
            }
        }

        const float* bias = biases[m];
        __nv_bfloat16* og = outs[m];
        #pragma unroll
        for (int g = 0; g < 16; g++) {
            int c = g * 8 + cq;
            float b0 = __ldg(bias + c), b1 = __ldg(bias + c + 1);
            u32 v0 = cvtbf((acc[g][1] + b1) * qs, (acc[g][0] + b0) * qs);
            u32 v1 = cvtbf((acc[g][3] + b1) * qs, (acc[g][2] + b0) * qs);
            *(u32*)&og[(size_t)ra * CC + c] = v0;
            *(u32*)&og[(size_t)(ra + 8) * CC + c] = v1;
        }
    }
}

// =====================================================================
// K+V tile loader, 256 threads, one cp.async group, buf in {0,1,2}
// =====================================================================
__device__ __forceinline__ void ldKV(u32 sb, const __nv_bfloat16* kg,
                                     const __nv_bfloat16* vg, int tid, int buf)
{
    u32 kb = sb + KS_OFF + (u32)buf * 16384u;
    u32 vb = sb + VS_OFF + (u32)buf * 16384u;
    #pragma unroll
    for (int i = 0; i < 4; i++) {
        int idx = tid + 256 * i; u32 row = (u32)(idx >> 4), c8 = (u32)(idx & 15);
        cpa16(kb + so(row, c8), kg + (size_t)row * CC + 8 * c8);
    }
    #pragma unroll
    for (int i = 0; i < 4; i++) {
        int idx = tid + 256 * i; u32 row = (u32)(idx >> 4), c8 = (u32)(idx & 15);
        cpa16(vb + so(row, c8), vg + (size_t)row * CC + 8 * c8);
    }
    cp_commit();
}

// =====================================================================
// Kernel 2: bf16 mma.sync flash attention + residual + BN
// grid (32, 8) = 256 CTAs, 256 threads (8 warps x 16 query rows)
// Triple-buffered KV, ONE barrier per tile.
// =====================================================================
__global__ void __launch_bounds__(256, 1) attn_mma(
    const float* __restrict__ x,
    const float* __restrict__ gamma, const float* __restrict__ beta,
    const float* __restrict__ mmean, const float* __restrict__ mvar,
    float* __restrict__ out)
{
    extern __shared__ char smc[];
    const u32 sb = s2u(smc);
    const int tid = threadIdx.x, w = tid >> 5, lane = tid & 31;
    const int r8 = lane & 7, sel = lane >> 3;
    const int b = blockIdx.y, q0 = blockIdx.x * QT;
    const size_t base = (size_t)b * NN * CC;

    if (tid < 128) {
        float iv = gamma[tid] * rsqrtf(mvar[tid] + 1e-3f);
        ((float*)(smc + BN_OFF))[tid] = iv;
        ((float*)(smc + BN_OFF + 512))[tid] = beta[tid] - mmean[tid] * iv;
    }

    // prologue: Q (group 0), KV0 (group 1), KV1 (group 2)
    {
        const __nv_bfloat16* qg = g_q + base + (size_t)q0 * CC;
        #pragma unroll
        for (int i = 0; i < 8; i++) {
            int idx = tid + 256 * i; u32 row = (u32)(idx >> 4), c8 = (u32)(idx & 15);
            cpa16(sb + QS_OFF + so(row, c8), qg + (size_t)row * CC + 8 * c8);
        }
        cp_commit();
    }
    ldKV(sb, g_k + base, g_v + base, tid, 0);
    ldKV(sb, g_k + base + (size_t)KTT * CC, g_v + base + (size_t)KTT * CC, tid, 1);

    cp_wait<2>();          // Q ready
    __syncthreads();

    u32 qa[8][4];
    #pragma unroll
    for (int s = 0; s < 8; s++) {
        u32 row = (u32)(w * 16 + r8 + (sel & 1) * 8);
        u32 ch  = (u32)(2 * s + (sel >> 1));
        ldsm4(sb + QS_OFF + so(row, ch), qa[s]);
    }

    float o[16][4];
    #pragma unroll
    for (int g = 0; g < 16; g++)
        { o[g][0] = 0.f; o[g][1] = 0.f; o[g][2] = 0.f; o[g][3] = 0.f; }
    float lr0 = 0.f, lr1 = 0.f;

    int bufj = 0;
    for (int j = 0; j < NTILE; j++) {
        cp_wait<1>();
        __syncthreads();     // KV(j) ready AND all warps done with tile j-1
        const u32 kb = sb + KS_OFF + (u32)bufj * 16384u;
        const u32 vb = sb + VS_OFF + (u32)bufj * 16384u;

        // ---- S = Q K^T ----
        float sc[8][4];
        #pragma unroll
        for (int g = 0; g < 8; g++)
            { sc[g][0] = 0.f; sc[g][1] = 0.f; sc[g][2] = 0.f; sc[g][3] = 0.f; }

        #pragma unroll
        for (int gp = 0; gp < 4; gp++) {
            #pragma unroll
            for (int s = 0; s < 8; s++) {
                u32 key = (u32)(gp * 16 + r8 + (sel >> 1) * 8);
                u32 ch  = (u32)(2 * s + (sel & 1));
                u32 kf[4];
                ldsm4(kb + so(key, ch), kf);
                mmabf(sc[2 * gp],     qa[s], kf[0], kf[1]);
                mmabf(sc[2 * gp + 1], qa[s], kf[2], kf[3]);
            }
        }

        // ---- softmax exp2-fused, pack P as A-fragments ----
        u32 p[4][4];
        #pragma unroll
        for (int g = 0; g < 8; g++) {
            float e0 = ex2(fmaf(sc[g][0], LOG2E, -EOFF * LOG2E));
            float e1 = ex2(fmaf(sc[g][1], LOG2E, -EOFF * LOG2E));
            float e2 = ex2(fmaf(sc[g][2], LOG2E, -EOFF * LOG2E));
            float e3 = ex2(fmaf(sc[g][3], LOG2E, -EOFF * LOG2E));
            lr0 += e0 + e1;
            lr1 += e2 + e3;
            p[g >> 1][(g & 1) ? 2 : 0] = cvtbf(e1, e0);
            p[g >> 1][(g & 1) ? 3 : 1] = cvtbf(e3, e2);
        }

        // ---- O += P V ----
        #pragma unroll
        for (int s = 0; s < 4; s++) {
            #pragma unroll
            for (int gp = 0; gp < 8; gp++) {
                u32 key = (u32)(s * 16 + r8 + (sel & 1) * 8);
                u32 ch  = (u32)(2 * gp + (sel >> 1));
                u32 vf[4];
                ldsm4t(vb + so(key, ch), vf);
                mmabf(o[2 * gp],     p[s], vf[0], vf[1]);
                mmabf(o[2 * gp + 1], p[s], vf[2], vf[3]);
            }
        }

        // issue KV(j+2) into buffer (j+2)%3 — safe w/o barrier (see theory)
        if (j + 2 < NTILE) {
            int nb = bufj + 2; if (nb >= 3) nb -= 3;
            ldKV(sb, g_k + base + (size_t)(j + 2) * KTT * CC,
                     g_v + base + (size_t)(j + 2) * KTT * CC, tid, nb);
        } else {
            cp_commit();     // keep per-thread group count uniform
        }
        if (++bufj == 3) bufj = 0;
    }

    // ---- epilogue ----
    lr0 += __shfl_xor_sync(0xffffffffu, lr0, 1);
    lr0 += __shfl_xor_sync(0xffffffffu, lr0, 2);
    lr1 += __shfl_xor_sync(0xffffffffu, lr1, 1);
    lr1 += __shfl_xor_sync(0xffffffffu, lr1, 2);
    const float il0 = 1.0f / lr0, il1 = 1.0f / lr1;

    const float* invc = (const float*)(smc + BN_OFF);
    const float* addc = (const float*)(smc + BN_OFF + 512);
    const int rr = lane >> 2, cq = (lane & 3) * 2;
    const int row0g = q0 + w * 16 + rr, row1g = row0g + 8;

    #pragma unroll
    for (int g = 0; g < 16; g++) {
        int c = g * 8 + cq;
        float2 x0 = *(const float2*)&x[base + (size_t)row0g * CC + c];
        float2 x1 = *(const float2*)&x[base + (size_t)row1g * CC + c];
        float2 v0, v1;
        v0.x = (o[g][0] * il0 + x0.x) * invc[c]     + addc[c];
        v0.y = (o[g][1] * il0 + x0.y) * invc[c + 1] + addc[c + 1];
        v1.x = (o[g][2] * il1 + x1.x) * invc[c]     + addc[c];
        v1.y = (o[g][3] * il1 + x1.y) * invc[c + 1] + addc[c + 1];
        *(float2*)&out[base + (size_t)row0g * CC + c] = v0;
        *(float2*)&out[base + (size_t)row1g * CC + c] = v1;
    }
}

// =====================================================================
extern "C" void kernel_launch(void* const* d_in, const int* in_sizes, int n_in,
                              void* d_out, int out_size)
{
    const float* x     = (const float*)d_in[0];
    const float* wq    = (const float*)d_in[1];
    const float* bq    = (const float*)d_in[2];
    const float* wk    = (const float*)d_in[3];
    const float* bk    = (const float*)d_in[4];
    const float* wv    = (const float*)d_in[5];
    const float* bv    = (const float*)d_in[6];
    const float* gamma = (const float*)d_in[7];
    const float* beta  = (const float*)d_in[8];
    const float* mmean = (const float*)d_in[9];
    const float* mvar  = (const float*)d_in[10];
    float* out = (float*)d_out;

    cudaFuncSetAttribute(qkv_mma, cudaFuncAttributeMaxDynamicSharedMemorySize, SMEM_QKV);
    cudaFuncSetAttribute(attn_mma, cudaFuncAttributeMaxDynamicSharedMemorySize, SMEM_ATTN);

    qkv_mma<<<(BB * NN) / 128, 256, SMEM_QKV>>>(x, wq, bq, wk, bk, wv, bv);
    attn_mma<<<dim3(NN / QT, BB), 256, SMEM_ATTN>>>(x, gamma, beta, mmean, mvar, out);
}